// round 2
// baseline (speedup 1.0000x reference)
#include <cuda_runtime.h>
#include <cstdint>
#include <cstddef>

#define EPSV 1e-5f
#define NUSERS_MAX 100000
#define NFOODS_MAX 50000

// Scratch (device globals, no allocations)
__device__ float g_U[(size_t)NUSERS_MAX * 128];  // (z_user @ W1a^T) * s
__device__ float g_F[(size_t)NFOODS_MAX * 128];  // (z_food @ W1b^T) * s
__device__ float g_C[128];                       // b1*s + beta - mean*s
__device__ int   g_is64;                         // index dtype flag

// ---------------------------------------------------------------------------
// Detect whether the index buffers are int64 (odd 32-bit words all zero)
// or int32. Deterministic: depends only on input content.
// ---------------------------------------------------------------------------
__global__ void detect_idx_dtype(const unsigned int* __restrict__ rowraw)
{
    int lane = threadIdx.x;          // 32 threads
    unsigned int v = rowraw[2 * lane + 1];   // odd words 1,3,...,63
    unsigned int any = __ballot_sync(0xffffffffu, v != 0u);
    if (lane == 0) g_is64 = (any == 0u) ? 1 : 0;
}

// ---------------------------------------------------------------------------
// GEMM: out[m][n] = s[n] * sum_k Z[m][k] * W[n*ldw + koff + k],  K=128, N=128
// BM=128, BN=128, BK=32, 256 threads, 8x8 per thread.
// ---------------------------------------------------------------------------
#define BM 128
#define BN 128
#define BK 32
#define SPAD 132

__global__ void __launch_bounds__(256, 2)
gemm_bn(const float* __restrict__ Z, int M,
        const float* __restrict__ W, int ldw, int koff,
        const float* __restrict__ gamma,
        const float* __restrict__ rvar,
        float* __restrict__ out)
{
    __shared__ float As[BK][SPAD];
    __shared__ float Ws[BK][SPAD];

    const int m0 = blockIdx.x * BM;
    const int t  = threadIdx.x;
    const int tx = t & 15;     // 0..15 -> n groups
    const int ty = t >> 4;     // 0..15 -> m groups

    float acc[8][8];
#pragma unroll
    for (int i = 0; i < 8; i++)
#pragma unroll
        for (int j = 0; j < 8; j++) acc[i][j] = 0.f;

    const int lr = t >> 3;          // 0..31 row within tile slice
    const int lk = (t & 7) * 4;     // 0..28 k offset

    for (int k0 = 0; k0 < 128; k0 += BK) {
#pragma unroll
        for (int r = 0; r < 4; r++) {
            int m = lr + 32 * r;
            float4 v = make_float4(0.f, 0.f, 0.f, 0.f);
            if (m0 + m < M)
                v = *(const float4*)(Z + (size_t)(m0 + m) * 128 + k0 + lk);
            As[lk + 0][m] = v.x; As[lk + 1][m] = v.y;
            As[lk + 2][m] = v.z; As[lk + 3][m] = v.w;
        }
#pragma unroll
        for (int r = 0; r < 4; r++) {
            int n = lr + 32 * r;
            float4 v = *(const float4*)(W + (size_t)n * ldw + koff + k0 + lk);
            Ws[lk + 0][n] = v.x; Ws[lk + 1][n] = v.y;
            Ws[lk + 2][n] = v.z; Ws[lk + 3][n] = v.w;
        }
        __syncthreads();

#pragma unroll
        for (int k = 0; k < BK; k++) {
            float a[8], b[8];
            *(float4*)&a[0] = *(const float4*)&As[k][4 * ty];
            *(float4*)&a[4] = *(const float4*)&As[k][64 + 4 * ty];
            *(float4*)&b[0] = *(const float4*)&Ws[k][4 * tx];
            *(float4*)&b[4] = *(const float4*)&Ws[k][64 + 4 * tx];
#pragma unroll
            for (int i = 0; i < 8; i++)
#pragma unroll
                for (int j = 0; j < 8; j++)
                    acc[i][j] += a[i] * b[j];
        }
        __syncthreads();
    }

    float s[8];
#pragma unroll
    for (int j = 0; j < 8; j++) {
        int n = (j < 4) ? (4 * tx + j) : (64 + 4 * tx + (j - 4));
        s[j] = gamma[n] * rsqrtf(rvar[n] + EPSV);
    }
#pragma unroll
    for (int i = 0; i < 8; i++) {
        int mloc = (i < 4) ? (4 * ty + i) : (64 + 4 * ty + (i - 4));
        int m = m0 + mloc;
        if (m < M) {
            float4 v0 = make_float4(acc[i][0] * s[0], acc[i][1] * s[1],
                                    acc[i][2] * s[2], acc[i][3] * s[3]);
            float4 v1 = make_float4(acc[i][4] * s[4], acc[i][5] * s[5],
                                    acc[i][6] * s[6], acc[i][7] * s[7]);
            *(float4*)(out + (size_t)m * 128 + 4 * tx)      = v0;
            *(float4*)(out + (size_t)m * 128 + 64 + 4 * tx) = v1;
        }
    }
}

// ---------------------------------------------------------------------------
// c[n] = b1[n]*s + beta[n] - mean[n]*s
// ---------------------------------------------------------------------------
__global__ void prep_c(const float* __restrict__ b1, const float* __restrict__ gamma,
                       const float* __restrict__ beta, const float* __restrict__ mean,
                       const float* __restrict__ var, float* __restrict__ C)
{
    int n = threadIdx.x;
    float s = gamma[n] * rsqrtf(var[n] + EPSV);
    C[n] = b1[n] * s + beta[n] - mean[n] * s;
}

// ---------------------------------------------------------------------------
// Edge kernel: warp per edge (grid-stride). 512B coalesced gathers from U, F.
// out[e] = sigmoid( W2 . relu(U[row]+F[col]+C) + b2 + 0.1 )
// ---------------------------------------------------------------------------
__global__ void __launch_bounds__(256)
edge_kernel(const float* __restrict__ U, const float* __restrict__ F,
            const void* __restrict__ rowp, const void* __restrict__ colp,
            const float* __restrict__ W2, const float* __restrict__ b2,
            const float* __restrict__ C, float* __restrict__ out,
            int E, int n_users, int n_foods)
{
    __shared__ float4 sW[32];
    __shared__ float4 sC[32];
    int t = threadIdx.x;
    if (t < 32) {
        sW[t] = ((const float4*)W2)[t];
        sC[t] = ((const float4*)C)[t];
    }
    __syncthreads();

    const int lane = t & 31;
    const int wpb  = blockDim.x >> 5;
    int warp = blockIdx.x * wpb + (t >> 5);
    const int nw = gridDim.x * wpb;

    const int is64 = g_is64;
    const float bias = b2[0] + 0.1f;
    const float4 w  = sW[lane];
    const float4 cc = sC[lane];

    const int*       row32 = (const int*)rowp;
    const int*       col32 = (const int*)colp;
    const long long* row64 = (const long long*)rowp;
    const long long* col64 = (const long long*)colp;

    for (int e = warp; e < E; e += nw) {
        long long ri = is64 ? row64[e] : (long long)row32[e];
        long long ci = is64 ? col64[e] : (long long)col32[e];
        // clamp defensively (mis-detection -> wrong answer, not crash)
        if (ri < 0) ri = 0; if (ri >= n_users) ri = n_users - 1;
        if (ci < 0) ci = 0; if (ci >= n_foods) ci = n_foods - 1;
        float4 u = *(const float4*)(U + (size_t)ri * 128 + lane * 4);
        float4 f = *(const float4*)(F + (size_t)ci * 128 + lane * 4);
        float x0 = fmaxf(u.x + f.x + cc.x, 0.f);
        float x1 = fmaxf(u.y + f.y + cc.y, 0.f);
        float x2 = fmaxf(u.z + f.z + cc.z, 0.f);
        float x3 = fmaxf(u.w + f.w + cc.w, 0.f);
        float dot = x0 * w.x + x1 * w.y + x2 * w.z + x3 * w.w;
#pragma unroll
        for (int o = 16; o > 0; o >>= 1)
            dot += __shfl_xor_sync(0xffffffffu, dot, o);
        if (lane == 0)
            out[e] = 1.f / (1.f + expf(-(dot + bias)));
    }
}

// ---------------------------------------------------------------------------
// kernel_launch
// Inputs (metadata order): z_user, z_food, row, col, W1, b1, gamma, beta,
//                          running_mean, running_var, W2, b2
// ---------------------------------------------------------------------------
extern "C" void kernel_launch(void* const* d_in, const int* in_sizes, int n_in,
                              void* d_out, int out_size)
{
    const float* z_user = (const float*)d_in[0];
    const float* z_food = (const float*)d_in[1];
    const void*  row    = d_in[2];
    const void*  col    = d_in[3];
    const float* W1     = (const float*)d_in[4];
    const float* b1     = (const float*)d_in[5];
    const float* gamma  = (const float*)d_in[6];
    const float* beta   = (const float*)d_in[7];
    const float* rmean  = (const float*)d_in[8];
    const float* rvar   = (const float*)d_in[9];
    const float* W2     = (const float*)d_in[10];
    const float* b2     = (const float*)d_in[11];
    float*       out    = (float*)d_out;

    int n_users = in_sizes[0] / 128;
    int n_foods = in_sizes[1] / 128;
    int E       = in_sizes[2];
    if (n_users > NUSERS_MAX) n_users = NUSERS_MAX;
    if (n_foods > NFOODS_MAX) n_foods = NFOODS_MAX;

    float *pU = nullptr, *pF = nullptr, *pC = nullptr;
    cudaGetSymbolAddress((void**)&pU, g_U);
    cudaGetSymbolAddress((void**)&pF, g_F);
    cudaGetSymbolAddress((void**)&pC, g_C);

    detect_idx_dtype<<<1, 32>>>((const unsigned int*)row);
    prep_c<<<1, 128>>>(b1, gamma, beta, rmean, rvar, pC);

    int gu = (n_users + BM - 1) / BM;
    int gf = (n_foods + BM - 1) / BM;
    gemm_bn<<<gu, 256>>>(z_user, n_users, W1, 256, 0,   gamma, rvar, pU);
    gemm_bn<<<gf, 256>>>(z_food, n_foods, W1, 256, 128, gamma, rvar, pF);

    int blocks = 148 * 8;
    edge_kernel<<<blocks, 256>>>(pU, pF, row, col, W2, b2, pC, out,
                                 E, n_users, n_foods);
}

// round 4
// speedup vs baseline: 1.1930x; 1.1930x over previous
#include <cuda_runtime.h>
#include <cuda_fp16.h>
#include <cstdint>
#include <cstddef>

#define EPSV 1e-5f
#define NUSERS_MAX 100000
#define NFOODS_MAX 50000

// Scratch (device globals, no allocations)
__device__ __half g_Uh[(size_t)NUSERS_MAX * 128];  // (z_user @ W1a^T) * s, fp16
__device__ __half g_Fh[(size_t)NFOODS_MAX * 128];  // (z_food @ W1b^T) * s, fp16
__device__ float  g_C[128];                        // b1*s + beta - mean*s
__device__ int    g_is64;                          // index dtype flag

__device__ __forceinline__ uint32_t tf32(float x) {
    uint32_t r;
    asm("cvt.rna.tf32.f32 %0, %1;" : "=r"(r) : "f"(x));
    return r;
}

__device__ __forceinline__ void mma_tf32(float d[4], uint32_t a0, uint32_t a1,
                                         uint32_t a2, uint32_t a3,
                                         uint32_t b0, uint32_t b1) {
    asm volatile(
        "mma.sync.aligned.m16n8k8.row.col.f32.tf32.tf32.f32 "
        "{%0,%1,%2,%3}, {%4,%5,%6,%7}, {%8,%9}, {%0,%1,%2,%3};"
        : "+f"(d[0]), "+f"(d[1]), "+f"(d[2]), "+f"(d[3])
        : "r"(a0), "r"(a1), "r"(a2), "r"(a3), "r"(b0), "r"(b1));
}

// ---------------------------------------------------------------------------
// Fused tf32 mma.sync GEMM producing both tables.
//   table[m][n] = half( s[n] * sum_k Z[m][k] * W1[n][koff+k] )
// Tile: 128x128x128 per CTA; 8 warps, each warp: rows [wid*16, wid*16+16).
//
// Smem layout (per 8-k-value group of row r, k-group kk):
//   word index = kk*1024 + r*8 + 4*((p>>2) ^ ((r>>2)&1)) + (p&3)
//   where p = pair-permuted position: p(w) puts k=kk*8+t at 2t, k+4 at 2t+1.
// Frag reads are lds.64 (k, k+4), conflict-free per phase.
// ---------------------------------------------------------------------------
__global__ void __launch_bounds__(256, 1)
gemm_mma(const float* __restrict__ zu, int Mu,
         const float* __restrict__ zf, int Mf,
         const float* __restrict__ W1,
         const float* __restrict__ gamma, const float* __restrict__ rvar,
         __half* __restrict__ Uh, __half* __restrict__ Fh, int tiles_u)
{
    extern __shared__ uint32_t smem[];     // As: [0,16384), Bs: [16384,32768)
    uint32_t* As = smem;
    uint32_t* Bs = smem + 16384;
    __shared__ float sS[128];

    int bid = blockIdx.x;
    const float* Z; int M; int koff; __half* out;
    if (bid < tiles_u) { Z = zu; M = Mu; koff = 0;   out = Uh; }
    else               { Z = zf; M = Mf; koff = 128; out = Fh; bid -= tiles_u; }
    const int m0 = bid * 128;

    const int tid  = threadIdx.x;
    const int wid  = tid >> 5;
    const int lane = tid & 31;

    if (tid < 128) sS[tid] = gamma[tid] * rsqrtf(rvar[tid] + EPSV);

    // ---- Fill smem (A tile and B tile), tf32-converted, permuted+swizzled ----
#pragma unroll
    for (int it = 0; it < 8; it++) {
        int g  = tid + it * 256;      // 0..2047 (row, kgroup) pairs
        int r  = g & 127;
        int kk = g >> 7;
        int sw = (r >> 2) & 1;
        uint32_t* baseA = As + kk * 1024 + r * 8;
        uint32_t* baseB = Bs + kk * 1024 + r * 8;

        // A: Z[m0+r][kk*8 .. +7]
        float4 lo = make_float4(0.f, 0.f, 0.f, 0.f);
        float4 hi = make_float4(0.f, 0.f, 0.f, 0.f);
        if (m0 + r < M) {
            lo = *(const float4*)(Z + (size_t)(m0 + r) * 128 + kk * 8);
            hi = *(const float4*)(Z + (size_t)(m0 + r) * 128 + kk * 8 + 4);
        }
        uint4 c0 = make_uint4(tf32(lo.x), tf32(hi.x), tf32(lo.y), tf32(hi.y));
        uint4 c1 = make_uint4(tf32(lo.z), tf32(hi.z), tf32(lo.w), tf32(hi.w));
        *(uint4*)(baseA + 4 * sw)       = c0;
        *(uint4*)(baseA + 4 * (1 - sw)) = c1;

        // B: W1[r][koff + kk*8 .. +7]   (r = output feature n)
        float4 bl = *(const float4*)(W1 + (size_t)r * 256 + koff + kk * 8);
        float4 bh = *(const float4*)(W1 + (size_t)r * 256 + koff + kk * 8 + 4);
        uint4 d0 = make_uint4(tf32(bl.x), tf32(bh.x), tf32(bl.y), tf32(bh.y));
        uint4 d1 = make_uint4(tf32(bl.z), tf32(bh.z), tf32(bl.w), tf32(bh.w));
        *(uint4*)(baseB + 4 * sw)       = d0;
        *(uint4*)(baseB + 4 * (1 - sw)) = d1;
    }
    __syncthreads();

    // ---- Compute: each warp 16 rows x 128 cols = 16 (m16n8) accumulators ----
    const int t  = lane & 3;
    const int qr = lane >> 2;
    const int ms = wid * 16;
    const int woff = 4 * (t >> 1) + ((2 * t) & 3);   // granule*4 + word (pre-swizzle)

    float acc[16][4];
#pragma unroll
    for (int j = 0; j < 16; j++)
#pragma unroll
        for (int q = 0; q < 4; q++) acc[j][q] = 0.f;

#pragma unroll
    for (int kk = 0; kk < 16; kk++) {
        int r0 = ms + qr, r1 = ms + qr + 8;
        // swizzle: XOR granule bit with (row>>2)&1
        uint32_t ia0 = kk * 1024 + r0 * 8 + (woff ^ (((r0 >> 2) & 1) << 2));
        uint32_t ia1 = kk * 1024 + r1 * 8 + (woff ^ (((r1 >> 2) & 1) << 2));
        uint2 aA = *(uint2*)(As + ia0);   // (a0, a2)
        uint2 aB = *(uint2*)(As + ia1);   // (a1, a3)
#pragma unroll
        for (int j = 0; j < 16; j++) {
            int n = j * 8 + qr;
            uint32_t ib = kk * 1024 + n * 8 + (woff ^ (((n >> 2) & 1) << 2));
            uint2 b = *(uint2*)(Bs + ib); // (b0, b1)
            mma_tf32(acc[j], aA.x, aB.x, aA.y, aB.y, b.x, b.y);
        }
    }

    // ---- Epilogue: scale by s[n], fp16, direct stores ----
#pragma unroll
    for (int j = 0; j < 16; j++) {
        int n0 = j * 8 + t * 2;
        float s0 = sS[n0], s1 = sS[n0 + 1];
        int r0 = m0 + ms + qr;
        int r1 = r0 + 8;
        if (r0 < M) {
            __half2 h = __floats2half2_rn(acc[j][0] * s0, acc[j][1] * s1);
            *(__half2*)(out + (size_t)r0 * 128 + n0) = h;
        }
        if (r1 < M) {
            __half2 h = __floats2half2_rn(acc[j][2] * s0, acc[j][3] * s1);
            *(__half2*)(out + (size_t)r1 * 128 + n0) = h;
        }
    }
}

// ---------------------------------------------------------------------------
// Detect int64 vs int32 index buffers (odd 32-bit words all zero -> int64)
// ---------------------------------------------------------------------------
__global__ void detect_idx_dtype(const unsigned int* __restrict__ rowraw)
{
    int lane = threadIdx.x;
    unsigned int v = rowraw[2 * lane + 1];
    unsigned int any = __ballot_sync(0xffffffffu, v != 0u);
    if (lane == 0) g_is64 = (any == 0u) ? 1 : 0;
}

// c[n] = b1[n]*s + beta[n] - mean[n]*s
__global__ void prep_c(const float* __restrict__ b1, const float* __restrict__ gamma,
                       const float* __restrict__ beta, const float* __restrict__ mean,
                       const float* __restrict__ var, float* __restrict__ C)
{
    int n = threadIdx.x;
    float s = gamma[n] * rsqrtf(var[n] + EPSV);
    C[n] = b1[n] * s + beta[n] - mean[n] * s;
}

// ---------------------------------------------------------------------------
// Edge kernel: warp per edge, 256B coalesced fp16 gathers from U, F.
// out[e] = sigmoid( W2 . relu(U[row]+F[col]+C) + b2 + 0.1 )
// ---------------------------------------------------------------------------
__global__ void __launch_bounds__(256)
edge_kernel(const __half* __restrict__ U, const __half* __restrict__ F,
            const void* __restrict__ rowp, const void* __restrict__ colp,
            const float* __restrict__ W2, const float* __restrict__ b2,
            const float* __restrict__ C, float* __restrict__ out,
            int E, int n_users, int n_foods)
{
    __shared__ float4 sW[32];
    __shared__ float4 sC[32];
    int t = threadIdx.x;
    if (t < 32) {
        sW[t] = ((const float4*)W2)[t];
        sC[t] = ((const float4*)C)[t];
    }
    __syncthreads();

    const int lane = t & 31;
    const int wpb  = blockDim.x >> 5;
    int warp = blockIdx.x * wpb + (t >> 5);
    const int nw = gridDim.x * wpb;

    const int is64 = g_is64;
    const float bias = b2[0] + 0.1f;
    const float4 w  = sW[lane];
    const float4 cc = sC[lane];

    const int*       row32 = (const int*)rowp;
    const int*       col32 = (const int*)colp;
    const long long* row64 = (const long long*)rowp;
    const long long* col64 = (const long long*)colp;
    const uint2* U2 = (const uint2*)U;
    const uint2* F2 = (const uint2*)F;

    for (int e = warp; e < E; e += nw) {
        long long ri = is64 ? row64[e] : (long long)row32[e];
        long long ci = is64 ? col64[e] : (long long)col32[e];
        if (ri < 0) ri = 0; if (ri >= n_users) ri = n_users - 1;
        if (ci < 0) ci = 0; if (ci >= n_foods) ci = n_foods - 1;
        uint2 uu = U2[(size_t)ri * 32 + lane];
        uint2 ff = F2[(size_t)ci * 32 + lane];
        float2 u0 = __half22float2(*(const __half2*)&uu.x);
        float2 u1 = __half22float2(*(const __half2*)&uu.y);
        float2 f0 = __half22float2(*(const __half2*)&ff.x);
        float2 f1 = __half22float2(*(const __half2*)&ff.y);
        float x0 = fmaxf(u0.x + f0.x + cc.x, 0.f);
        float x1 = fmaxf(u0.y + f0.y + cc.y, 0.f);
        float x2 = fmaxf(u1.x + f1.x + cc.z, 0.f);
        float x3 = fmaxf(u1.y + f1.y + cc.w, 0.f);
        float dot = x0 * w.x + x1 * w.y + x2 * w.z + x3 * w.w;
#pragma unroll
        for (int o = 16; o > 0; o >>= 1)
            dot += __shfl_xor_sync(0xffffffffu, dot, o);
        if (lane == 0)
            out[e] = 1.f / (1.f + expf(-(dot + bias)));
    }
}

// ---------------------------------------------------------------------------
// kernel_launch
// Inputs: z_user, z_food, row, col, W1, b1, gamma, beta, rmean, rvar, W2, b2
// ---------------------------------------------------------------------------
extern "C" void kernel_launch(void* const* d_in, const int* in_sizes, int n_in,
                              void* d_out, int out_size)
{
    const float* z_user = (const float*)d_in[0];
    const float* z_food = (const float*)d_in[1];
    const void*  row    = d_in[2];
    const void*  col    = d_in[3];
    const float* W1     = (const float*)d_in[4];
    const float* b1     = (const float*)d_in[5];
    const float* gamma  = (const float*)d_in[6];
    const float* beta   = (const float*)d_in[7];
    const float* rmean  = (const float*)d_in[8];
    const float* rvar   = (const float*)d_in[9];
    const float* W2     = (const float*)d_in[10];
    const float* b2     = (const float*)d_in[11];
    float*       out    = (float*)d_out;

    int n_users = in_sizes[0] / 128;
    int n_foods = in_sizes[1] / 128;
    int E       = in_sizes[2];
    if (n_users > NUSERS_MAX) n_users = NUSERS_MAX;
    if (n_foods > NFOODS_MAX) n_foods = NFOODS_MAX;

    __half *pU = nullptr, *pF = nullptr;
    float *pC = nullptr;
    cudaGetSymbolAddress((void**)&pU, g_Uh);
    cudaGetSymbolAddress((void**)&pF, g_Fh);
    cudaGetSymbolAddress((void**)&pC, g_C);

    detect_idx_dtype<<<1, 32>>>((const unsigned int*)row);
    prep_c<<<1, 128>>>(b1, gamma, beta, rmean, rvar, pC);

    int tiles_u = (n_users + 127) / 128;
    int tiles_f = (n_foods + 127) / 128;
    int smem = 32768 * sizeof(uint32_t);   // 128 KB
    cudaFuncSetAttribute(gemm_mma, cudaFuncAttributeMaxDynamicSharedMemorySize, smem);
    gemm_mma<<<tiles_u + tiles_f, 256, smem>>>(z_user, n_users, z_food, n_foods,
                                               W1, gamma, rvar, pU, pF, tiles_u);

    int blocks = 148 * 8;
    edge_kernel<<<blocks, 256>>>(pU, pF, row, col, W2, b2, pC, out,
                                 E, n_users, n_foods);
}

// round 5
// speedup vs baseline: 1.7278x; 1.4484x over previous
#include <cuda_runtime.h>
#include <cuda_fp16.h>
#include <cstdint>
#include <cstddef>

#define EPSV 1e-5f
#define NUSERS_MAX 100000
#define NFOODS_MAX 50000

// Scratch (device globals, no allocations)
__device__ __align__(16) __half g_Uh[(size_t)NUSERS_MAX * 128];
__device__ __align__(16) __half g_Fh[(size_t)NFOODS_MAX * 128];
__device__ float  g_C[128];
__device__ int    g_is64;

__device__ __forceinline__ uint32_t tf32(float x) {
    uint32_t r;
    asm("cvt.rna.tf32.f32 %0, %1;" : "=r"(r) : "f"(x));
    return r;
}

__device__ __forceinline__ void mma_tf32(float d[4], uint32_t a0, uint32_t a1,
                                         uint32_t a2, uint32_t a3,
                                         uint32_t b0, uint32_t b1) {
    asm volatile(
        "mma.sync.aligned.m16n8k8.row.col.f32.tf32.tf32.f32 "
        "{%0,%1,%2,%3}, {%4,%5,%6,%7}, {%8,%9}, {%0,%1,%2,%3};"
        : "+f"(d[0]), "+f"(d[1]), "+f"(d[2]), "+f"(d[3])
        : "r"(a0), "r"(a1), "r"(a2), "r"(a3), "r"(b0), "r"(b1));
}

// ---------------------------------------------------------------------------
// Fused tf32 mma.sync GEMM, K split into two 64-chunks (64 KB smem -> 2 CTA/SM)
//   table[m][n] = half( s[n] * sum_k Z[m][k] * W1[n][koff+k] )
// Tile: 128x128 per CTA; 8 warps, warp = rows [wid*16, wid*16+16) x 128 cols.
// Smem word idx per (row r, kgroup kg): kg*1024 + r*8 + (pos ^ swizzle)
// pair-permuted so frag reads are lds.64 (k, k+4), conflict-free.
// ---------------------------------------------------------------------------
__global__ void __launch_bounds__(256, 2)
gemm_mma(const float* __restrict__ zu, int Mu,
         const float* __restrict__ zf, int Mf,
         const float* __restrict__ W1,
         const float* __restrict__ gamma, const float* __restrict__ rvar,
         __half* __restrict__ Uh, __half* __restrict__ Fh, int tiles_u)
{
    extern __shared__ uint32_t smem[];     // As: [0,8192), Bs: [8192,16384)
    uint32_t* As = smem;
    uint32_t* Bs = smem + 8192;
    __shared__ float sS[128];

    int bid = blockIdx.x;
    const float* Z; int M; int koff; __half* out;
    if (bid < tiles_u) { Z = zu; M = Mu; koff = 0;   out = Uh; }
    else               { Z = zf; M = Mf; koff = 128; out = Fh; bid -= tiles_u; }
    const int m0 = bid * 128;

    const int tid  = threadIdx.x;
    const int wid  = tid >> 5;
    const int lane = tid & 31;

    if (tid < 128) sS[tid] = gamma[tid] * rsqrtf(rvar[tid] + EPSV);

    const int t  = lane & 3;
    const int qr = lane >> 2;
    const int ms = wid * 16;
    const int woff = 4 * (t >> 1) + ((2 * t) & 3);

    float acc[16][4];
#pragma unroll
    for (int j = 0; j < 16; j++)
#pragma unroll
        for (int q = 0; q < 4; q++) acc[j][q] = 0.f;

    for (int kc = 0; kc < 2; kc++) {
        // ---- fill 64-k chunk ----
#pragma unroll
        for (int it = 0; it < 4; it++) {
            int g  = tid + it * 256;      // 0..1023 (row, kgroup)
            int r  = g & 127;
            int kg = g >> 7;              // 0..7
            int k  = kc * 64 + kg * 8;
            int sw = (r >> 2) & 1;
            uint32_t* baseA = As + kg * 1024 + r * 8;
            uint32_t* baseB = Bs + kg * 1024 + r * 8;

            float4 lo = make_float4(0.f, 0.f, 0.f, 0.f);
            float4 hi = make_float4(0.f, 0.f, 0.f, 0.f);
            if (m0 + r < M) {
                lo = *(const float4*)(Z + (size_t)(m0 + r) * 128 + k);
                hi = *(const float4*)(Z + (size_t)(m0 + r) * 128 + k + 4);
            }
            uint4 c0 = make_uint4(tf32(lo.x), tf32(hi.x), tf32(lo.y), tf32(hi.y));
            uint4 c1 = make_uint4(tf32(lo.z), tf32(hi.z), tf32(lo.w), tf32(hi.w));
            *(uint4*)(baseA + 4 * sw)       = c0;
            *(uint4*)(baseA + 4 * (1 - sw)) = c1;

            float4 bl = *(const float4*)(W1 + (size_t)r * 256 + koff + k);
            float4 bh = *(const float4*)(W1 + (size_t)r * 256 + koff + k + 4);
            uint4 d0 = make_uint4(tf32(bl.x), tf32(bh.x), tf32(bl.y), tf32(bh.y));
            uint4 d1 = make_uint4(tf32(bl.z), tf32(bh.z), tf32(bl.w), tf32(bh.w));
            *(uint4*)(baseB + 4 * sw)       = d0;
            *(uint4*)(baseB + 4 * (1 - sw)) = d1;
        }
        __syncthreads();

        // ---- compute chunk ----
#pragma unroll
        for (int kk = 0; kk < 8; kk++) {
            int r0 = ms + qr, r1 = ms + qr + 8;
            uint32_t ia0 = kk * 1024 + r0 * 8 + (woff ^ (((r0 >> 2) & 1) << 2));
            uint32_t ia1 = kk * 1024 + r1 * 8 + (woff ^ (((r1 >> 2) & 1) << 2));
            uint2 aA = *(uint2*)(As + ia0);
            uint2 aB = *(uint2*)(As + ia1);
#pragma unroll
            for (int j = 0; j < 16; j++) {
                int n = j * 8 + qr;
                uint32_t ib = kk * 1024 + n * 8 + (woff ^ (((n >> 2) & 1) << 2));
                uint2 b = *(uint2*)(Bs + ib);
                mma_tf32(acc[j], aA.x, aB.x, aA.y, aB.y, b.x, b.y);
            }
        }
        __syncthreads();
    }

    // ---- epilogue: scale by s[n], fp16, direct stores ----
#pragma unroll
    for (int j = 0; j < 16; j++) {
        int n0 = j * 8 + t * 2;
        float s0 = sS[n0], s1 = sS[n0 + 1];
        int r0 = m0 + ms + qr;
        int r1 = r0 + 8;
        if (r0 < M) {
            __half2 h = __floats2half2_rn(acc[j][0] * s0, acc[j][1] * s1);
            *(__half2*)(out + (size_t)r0 * 128 + n0) = h;
        }
        if (r1 < M) {
            __half2 h = __floats2half2_rn(acc[j][2] * s0, acc[j][3] * s1);
            *(__half2*)(out + (size_t)r1 * 128 + n0) = h;
        }
    }
}

// ---------------------------------------------------------------------------
// Detect int64 vs int32 index buffers (odd 32-bit words all zero -> int64)
// ---------------------------------------------------------------------------
__global__ void detect_idx_dtype(const unsigned int* __restrict__ rowraw)
{
    int lane = threadIdx.x;
    unsigned int v = rowraw[2 * lane + 1];
    unsigned int any = __ballot_sync(0xffffffffu, v != 0u);
    if (lane == 0) g_is64 = (any == 0u) ? 1 : 0;
}

// c[n] = b1[n]*s + beta[n] - mean[n]*s
__global__ void prep_c(const float* __restrict__ b1, const float* __restrict__ gamma,
                       const float* __restrict__ beta, const float* __restrict__ mean,
                       const float* __restrict__ var, float* __restrict__ C)
{
    int n = threadIdx.x;
    float s = gamma[n] * rsqrtf(var[n] + EPSV);
    C[n] = b1[n] * s + beta[n] - mean[n] * s;
}

// ---------------------------------------------------------------------------
// Edge kernel: 4 edges per warp, 8 lanes per edge (32B of fp16 per lane).
// half2 add/relu, fp32 dot, 3-level shfl reduce within 8-lane groups.
// ---------------------------------------------------------------------------
__device__ __forceinline__ void acc2(float& dot, uint32_t u, uint32_t f,
                                     __half2 c, float w0, float w1, __half2 z2)
{
    __half2 h = __hadd2(__hadd2(*(__half2*)&u, *(__half2*)&f), c);
    h = __hmax2(h, z2);
    float2 v = __half22float2(h);
    dot = fmaf(v.x, w0, dot);
    dot = fmaf(v.y, w1, dot);
}

__global__ void __launch_bounds__(256)
edge_kernel(const __half* __restrict__ U, const __half* __restrict__ F,
            const void* __restrict__ rowp, const void* __restrict__ colp,
            const float* __restrict__ W2, const float* __restrict__ b2,
            const float* __restrict__ C, float* __restrict__ out,
            int E, int n_users, int n_foods)
{
    __shared__ float   sW[128];
    __shared__ __half2 sC[64];
    int tid = threadIdx.x;
    if (tid < 128) sW[tid] = W2[tid];
    if (tid < 64) {
        float2 c2 = ((const float2*)C)[tid];
        sC[tid] = __floats2half2_rn(c2.x, c2.y);
    }
    __syncthreads();

    const int lane = tid & 31;
    const int sub  = lane & 7;    // position within edge (16 halves each)
    const int g    = lane >> 3;   // edge within quad

    float w[16];
    __half2 c[8];
#pragma unroll
    for (int i = 0; i < 16; i++) w[i] = sW[sub * 16 + i];
#pragma unroll
    for (int i = 0; i < 8; i++)  c[i] = sC[sub * 8 + i];
    const __half2 z2 = __half2half2(__ushort_as_half(0));

    int warp = blockIdx.x * 8 + (tid >> 5);
    const int nw = gridDim.x * 8;
    const int is64 = g_is64;
    const float bias = b2[0] + 0.1f;

    const int*       row32 = (const int*)rowp;
    const int*       col32 = (const int*)colp;
    const long long* row64 = (const long long*)rowp;
    const long long* col64 = (const long long*)colp;
    const uint4* U4 = (const uint4*)U;
    const uint4* F4 = (const uint4*)F;

    for (int e0 = warp * 4; e0 < E; e0 += nw * 4) {
        int e = e0 + g;
        bool valid = e < E;
        int ee = valid ? e : (E - 1);
        long long ri = is64 ? row64[ee] : (long long)row32[ee];
        long long ci = is64 ? col64[ee] : (long long)col32[ee];
        if (ri < 0) ri = 0; if (ri >= n_users) ri = n_users - 1;
        if (ci < 0) ci = 0; if (ci >= n_foods) ci = n_foods - 1;

        size_t ub = (size_t)ri * 16 + sub * 2;   // row = 16 uint4
        size_t fb = (size_t)ci * 16 + sub * 2;
        uint4 u0 = U4[ub], u1 = U4[ub + 1];
        uint4 f0 = F4[fb], f1 = F4[fb + 1];

        float dot = 0.f;
        acc2(dot, u0.x, f0.x, c[0], w[0],  w[1],  z2);
        acc2(dot, u0.y, f0.y, c[1], w[2],  w[3],  z2);
        acc2(dot, u0.z, f0.z, c[2], w[4],  w[5],  z2);
        acc2(dot, u0.w, f0.w, c[3], w[6],  w[7],  z2);
        acc2(dot, u1.x, f1.x, c[4], w[8],  w[9],  z2);
        acc2(dot, u1.y, f1.y, c[5], w[10], w[11], z2);
        acc2(dot, u1.z, f1.z, c[6], w[12], w[13], z2);
        acc2(dot, u1.w, f1.w, c[7], w[14], w[15], z2);

        dot += __shfl_xor_sync(0xffffffffu, dot, 4);
        dot += __shfl_xor_sync(0xffffffffu, dot, 2);
        dot += __shfl_xor_sync(0xffffffffu, dot, 1);

        if (sub == 0 && valid)
            out[e] = 1.f / (1.f + __expf(-(dot + bias)));
    }
}

// ---------------------------------------------------------------------------
// kernel_launch
// Inputs: z_user, z_food, row, col, W1, b1, gamma, beta, rmean, rvar, W2, b2
// ---------------------------------------------------------------------------
extern "C" void kernel_launch(void* const* d_in, const int* in_sizes, int n_in,
                              void* d_out, int out_size)
{
    const float* z_user = (const float*)d_in[0];
    const float* z_food = (const float*)d_in[1];
    const void*  row    = d_in[2];
    const void*  col    = d_in[3];
    const float* W1     = (const float*)d_in[4];
    const float* b1     = (const float*)d_in[5];
    const float* gamma  = (const float*)d_in[6];
    const float* beta   = (const float*)d_in[7];
    const float* rmean  = (const float*)d_in[8];
    const float* rvar   = (const float*)d_in[9];
    const float* W2     = (const float*)d_in[10];
    const float* b2     = (const float*)d_in[11];
    float*       out    = (float*)d_out;

    int n_users = in_sizes[0] / 128;
    int n_foods = in_sizes[1] / 128;
    int E       = in_sizes[2];
    if (n_users > NUSERS_MAX) n_users = NUSERS_MAX;
    if (n_foods > NFOODS_MAX) n_foods = NFOODS_MAX;

    __half *pU = nullptr, *pF = nullptr;
    float *pC = nullptr;
    cudaGetSymbolAddress((void**)&pU, g_Uh);
    cudaGetSymbolAddress((void**)&pF, g_Fh);
    cudaGetSymbolAddress((void**)&pC, g_C);

    detect_idx_dtype<<<1, 32>>>((const unsigned int*)row);
    prep_c<<<1, 128>>>(b1, gamma, beta, rmean, rvar, pC);

    int tiles_u = (n_users + 127) / 128;
    int tiles_f = (n_foods + 127) / 128;
    int smem = 16384 * sizeof(uint32_t);   // 64 KB
    cudaFuncSetAttribute(gemm_mma, cudaFuncAttributeMaxDynamicSharedMemorySize, smem);
    gemm_mma<<<tiles_u + tiles_f, 256, smem>>>(z_user, n_users, z_food, n_foods,
                                               W1, gamma, rvar, pU, pF, tiles_u);

    int blocks = 148 * 8;
    edge_kernel<<<blocks, 256>>>(pU, pF, row, col, W2, b2, pC, out,
                                 E, n_users, n_foods);
}

// round 6
// speedup vs baseline: 2.1865x; 1.2655x over previous
#include <cuda_runtime.h>
#include <cuda_fp16.h>
#include <cstdint>
#include <cstddef>

#define EPSV 1e-5f
#define NUSERS_MAX 100000
#define NFOODS_MAX 50000

// Scratch (device globals, no allocations)
__device__ __align__(16) __half g_Uh[(size_t)NUSERS_MAX * 128];
__device__ __align__(16) __half g_Fh[(size_t)NFOODS_MAX * 128];
__device__ float  g_C[128];
__device__ int    g_is64;

__device__ __forceinline__ uint32_t smem_u32(const void* p) {
    uint32_t a;
    asm("{ .reg .u64 t; cvta.to.shared.u64 t, %1; cvt.u32.u64 %0, t; }"
        : "=r"(a) : "l"(p));
    return a;
}

__device__ __forceinline__ void ldm_x4(uint32_t& r0, uint32_t& r1,
                                       uint32_t& r2, uint32_t& r3, uint32_t a) {
    asm volatile("ldmatrix.sync.aligned.m8n8.x4.shared.b16 {%0,%1,%2,%3}, [%4];"
                 : "=r"(r0), "=r"(r1), "=r"(r2), "=r"(r3) : "r"(a));
}

__device__ __forceinline__ void mma_f16(float d[4], uint32_t a0, uint32_t a1,
                                        uint32_t a2, uint32_t a3,
                                        uint32_t b0, uint32_t b1) {
    asm volatile(
        "mma.sync.aligned.m16n8k16.row.col.f32.f16.f16.f32 "
        "{%0,%1,%2,%3}, {%4,%5,%6,%7}, {%8,%9}, {%0,%1,%2,%3};"
        : "+f"(d[0]), "+f"(d[1]), "+f"(d[2]), "+f"(d[3])
        : "r"(a0), "r"(a1), "r"(a2), "r"(a3), "r"(b0), "r"(b1));
}

// phys 16B-chunk index: XOR low 3 bits with row (conflict-free ldmatrix phases)
__device__ __forceinline__ int pchunk(int kc, int r) {
    return (kc & 8) | ((kc ^ r) & 7);
}

// ---------------------------------------------------------------------------
// fp16 HMMA GEMM: 128x128 tile per CTA, K=128 in one smem fill (64 KB).
//   table[m][n] = half( s[n] * sum_k Z[m][k] * W1[n][koff+k] )
// 8 warps, warp w = rows [w*16, w*16+16) x all 128 cols.
// Smem half layout: row r (256B) at r*256, 16B chunk kc at pchunk(kc,r)*16.
// ---------------------------------------------------------------------------
__global__ void __launch_bounds__(256)
gemm_mma(const float* __restrict__ zu, int Mu,
         const float* __restrict__ zf, int Mf,
         const float* __restrict__ W1,
         const float* __restrict__ gamma, const float* __restrict__ rvar,
         __half* __restrict__ Uh, __half* __restrict__ Fh, int tiles_u)
{
    extern __shared__ char smem[];     // A: [0,32768), B: [32768,65536)
    char* Ab = smem;
    char* Bb = smem + 32768;
    __shared__ float sS[128];

    int bid = blockIdx.x;
    const float* Z; int M; int koff; __half* out;
    if (bid < tiles_u) { Z = zu; M = Mu; koff = 0;   out = Uh; }
    else               { Z = zf; M = Mf; koff = 128; out = Fh; bid -= tiles_u; }
    const int m0 = bid * 128;

    const int tid  = threadIdx.x;
    const int wrp  = tid >> 5;
    const int lane = tid & 31;

    if (tid < 128) sS[tid] = gamma[tid] * rsqrtf(rvar[tid] + EPSV);

    // ---- fill: thread (kc = tid&15, row = tid>>4 + 16*pass) ----
    {
        const int kc = tid & 15;
        const int rb = tid >> 4;
#pragma unroll
        for (int pass = 0; pass < 8; pass++) {
            int r = rb + pass * 16;
            int pc16 = pchunk(kc, r) * 16;

            float4 lo = make_float4(0.f, 0.f, 0.f, 0.f);
            float4 hi = make_float4(0.f, 0.f, 0.f, 0.f);
            if (m0 + r < M) {
                lo = *(const float4*)(Z + (size_t)(m0 + r) * 128 + kc * 8);
                hi = *(const float4*)(Z + (size_t)(m0 + r) * 128 + kc * 8 + 4);
            }
            __half2 a0 = __floats2half2_rn(lo.x, lo.y);
            __half2 a1 = __floats2half2_rn(lo.z, lo.w);
            __half2 a2 = __floats2half2_rn(hi.x, hi.y);
            __half2 a3 = __floats2half2_rn(hi.z, hi.w);
            uint4 pa;
            pa.x = *(uint32_t*)&a0; pa.y = *(uint32_t*)&a1;
            pa.z = *(uint32_t*)&a2; pa.w = *(uint32_t*)&a3;
            *(uint4*)(Ab + r * 256 + pc16) = pa;

            float4 bl = *(const float4*)(W1 + (size_t)r * 256 + koff + kc * 8);
            float4 bh = *(const float4*)(W1 + (size_t)r * 256 + koff + kc * 8 + 4);
            __half2 b0 = __floats2half2_rn(bl.x, bl.y);
            __half2 b1 = __floats2half2_rn(bl.z, bl.w);
            __half2 b2 = __floats2half2_rn(bh.x, bh.y);
            __half2 b3 = __floats2half2_rn(bh.z, bh.w);
            uint4 pb;
            pb.x = *(uint32_t*)&b0; pb.y = *(uint32_t*)&b1;
            pb.z = *(uint32_t*)&b2; pb.w = *(uint32_t*)&b3;
            *(uint4*)(Bb + r * 256 + pc16) = pb;
        }
    }
    __syncthreads();

    // ---- compute ----
    const uint32_t Au = smem_u32(Ab);
    const uint32_t Bu = Au + 32768;
    const int g   = lane >> 3;    // ldmatrix group 0..3
    const int idx = lane & 7;

    float acc[16][4];
#pragma unroll
    for (int j = 0; j < 16; j++)
#pragma unroll
        for (int q = 0; q < 4; q++) acc[j][q] = 0.f;

#pragma unroll
    for (int kk = 0; kk < 8; kk++) {
        // A frag: groups (rows lo/hi) x (kc lo/hi)
        int ar  = wrp * 16 + (g & 1) * 8 + idx;
        int akc = kk * 2 + (g >> 1);
        uint32_t a0, a1, a2, a3;
        ldm_x4(a0, a1, a2, a3, Au + ar * 256 + pchunk(akc, ar) * 16);

#pragma unroll
        for (int jj = 0; jj < 8; jj++) {
            // B x4: g0/g1 = n-tile lo (kc0,kc1); g2/g3 = n-tile hi
            int bn  = jj * 16 + (g >> 1) * 8 + idx;
            int bkc = kk * 2 + (g & 1);
            uint32_t b0, b1, b2, b3;
            ldm_x4(b0, b1, b2, b3, Bu + bn * 256 + pchunk(bkc, bn) * 16);
            mma_f16(acc[2 * jj],     a0, a1, a2, a3, b0, b1);
            mma_f16(acc[2 * jj + 1], a0, a1, a2, a3, b2, b3);
        }
    }

    // ---- epilogue ----
    const int t  = lane & 3;
    const int qr = lane >> 2;
#pragma unroll
    for (int j = 0; j < 16; j++) {
        int n0 = j * 8 + 2 * t;
        float s0 = sS[n0], s1 = sS[n0 + 1];
        int r0 = m0 + wrp * 16 + qr;
        int r1 = r0 + 8;
        if (r0 < M) {
            __half2 h = __floats2half2_rn(acc[j][0] * s0, acc[j][1] * s1);
            *(__half2*)(out + (size_t)r0 * 128 + n0) = h;
        }
        if (r1 < M) {
            __half2 h = __floats2half2_rn(acc[j][2] * s0, acc[j][3] * s1);
            *(__half2*)(out + (size_t)r1 * 128 + n0) = h;
        }
    }
}

// ---------------------------------------------------------------------------
// Detect int64 vs int32 index buffers (odd 32-bit words all zero -> int64)
// ---------------------------------------------------------------------------
__global__ void detect_idx_dtype(const unsigned int* __restrict__ rowraw)
{
    int lane = threadIdx.x;
    unsigned int v = rowraw[2 * lane + 1];
    unsigned int any = __ballot_sync(0xffffffffu, v != 0u);
    if (lane == 0) g_is64 = (any == 0u) ? 1 : 0;
}

// c[n] = b1[n]*s + beta[n] - mean[n]*s
__global__ void prep_c(const float* __restrict__ b1, const float* __restrict__ gamma,
                       const float* __restrict__ beta, const float* __restrict__ mean,
                       const float* __restrict__ var, float* __restrict__ C)
{
    int n = threadIdx.x;
    float s = gamma[n] * rsqrtf(var[n] + EPSV);
    C[n] = b1[n] * s + beta[n] - mean[n] * s;
}

// ---------------------------------------------------------------------------
// Edge kernel: 2 edges per warp, 16 lanes per edge (one uint4 per table).
// ---------------------------------------------------------------------------
__device__ __forceinline__ void acc2(float& dot, uint32_t u, uint32_t f,
                                     __half2 c, float w0, float w1, __half2 z2)
{
    __half2 h = __hadd2(__hadd2(*(__half2*)&u, *(__half2*)&f), c);
    h = __hmax2(h, z2);
    float2 v = __half22float2(h);
    dot = fmaf(v.x, w0, dot);
    dot = fmaf(v.y, w1, dot);
}

__global__ void __launch_bounds__(256)
edge_kernel(const __half* __restrict__ U, const __half* __restrict__ F,
            const void* __restrict__ rowp, const void* __restrict__ colp,
            const float* __restrict__ W2, const float* __restrict__ b2,
            const float* __restrict__ C, float* __restrict__ out,
            int E, int n_users, int n_foods)
{
    __shared__ float   sW[128];
    __shared__ __half2 sC[64];
    int tid = threadIdx.x;
    if (tid < 128) sW[tid] = W2[tid];
    if (tid < 64) {
        float2 c2 = ((const float2*)C)[tid];
        sC[tid] = __floats2half2_rn(c2.x, c2.y);
    }
    __syncthreads();

    const int lane = tid & 31;
    const int sub  = lane & 15;   // position within edge (8 halves)
    const int g    = lane >> 4;   // edge within pair

    float w[8];
    __half2 c[4];
#pragma unroll
    for (int i = 0; i < 8; i++) w[i] = sW[sub * 8 + i];
#pragma unroll
    for (int i = 0; i < 4; i++) c[i] = sC[sub * 4 + i];
    const __half2 z2 = __half2half2(__ushort_as_half(0));

    int warp = blockIdx.x * 8 + (tid >> 5);
    const int nw = gridDim.x * 8;
    const int is64 = g_is64;
    const float bias = b2[0] + 0.1f;

    const int*       row32 = (const int*)rowp;
    const int*       col32 = (const int*)colp;
    const long long* row64 = (const long long*)rowp;
    const long long* col64 = (const long long*)colp;
    const uint4* U4 = (const uint4*)U;
    const uint4* F4 = (const uint4*)F;

    for (int e0 = warp * 2; e0 < E; e0 += nw * 2) {
        int e = e0 + g;
        bool valid = e < E;
        int ee = valid ? e : (E - 1);
        long long ri = is64 ? row64[ee] : (long long)row32[ee];
        long long ci = is64 ? col64[ee] : (long long)col32[ee];
        if (ri < 0) ri = 0; if (ri >= n_users) ri = n_users - 1;
        if (ci < 0) ci = 0; if (ci >= n_foods) ci = n_foods - 1;

        uint4 u0 = U4[(size_t)ri * 16 + sub];
        uint4 f0 = F4[(size_t)ci * 16 + sub];

        float dot = 0.f;
        acc2(dot, u0.x, f0.x, c[0], w[0], w[1], z2);
        acc2(dot, u0.y, f0.y, c[1], w[2], w[3], z2);
        acc2(dot, u0.z, f0.z, c[2], w[4], w[5], z2);
        acc2(dot, u0.w, f0.w, c[3], w[6], w[7], z2);

        dot += __shfl_xor_sync(0xffffffffu, dot, 8);
        dot += __shfl_xor_sync(0xffffffffu, dot, 4);
        dot += __shfl_xor_sync(0xffffffffu, dot, 2);
        dot += __shfl_xor_sync(0xffffffffu, dot, 1);

        if (sub == 0 && valid)
            out[e] = 1.f / (1.f + __expf(-(dot + bias)));
    }
}

// ---------------------------------------------------------------------------
// kernel_launch
// Inputs: z_user, z_food, row, col, W1, b1, gamma, beta, rmean, rvar, W2, b2
// ---------------------------------------------------------------------------
extern "C" void kernel_launch(void* const* d_in, const int* in_sizes, int n_in,
                              void* d_out, int out_size)
{
    const float* z_user = (const float*)d_in[0];
    const float* z_food = (const float*)d_in[1];
    const void*  row    = d_in[2];
    const void*  col    = d_in[3];
    const float* W1     = (const float*)d_in[4];
    const float* b1     = (const float*)d_in[5];
    const float* gamma  = (const float*)d_in[6];
    const float* beta   = (const float*)d_in[7];
    const float* rmean  = (const float*)d_in[8];
    const float* rvar   = (const float*)d_in[9];
    const float* W2     = (const float*)d_in[10];
    const float* b2     = (const float*)d_in[11];
    float*       out    = (float*)d_out;

    int n_users = in_sizes[0] / 128;
    int n_foods = in_sizes[1] / 128;
    int E       = in_sizes[2];
    if (n_users > NUSERS_MAX) n_users = NUSERS_MAX;
    if (n_foods > NFOODS_MAX) n_foods = NFOODS_MAX;

    __half *pU = nullptr, *pF = nullptr;
    float *pC = nullptr;
    cudaGetSymbolAddress((void**)&pU, g_Uh);
    cudaGetSymbolAddress((void**)&pF, g_Fh);
    cudaGetSymbolAddress((void**)&pC, g_C);

    detect_idx_dtype<<<1, 32>>>((const unsigned int*)row);
    prep_c<<<1, 128>>>(b1, gamma, beta, rmean, rvar, pC);

    int tiles_u = (n_users + 127) / 128;
    int tiles_f = (n_foods + 127) / 128;
    int smem = 65536;
    cudaFuncSetAttribute(gemm_mma, cudaFuncAttributeMaxDynamicSharedMemorySize, smem);
    gemm_mma<<<tiles_u + tiles_f, 256, smem>>>(z_user, n_users, z_food, n_foods,
                                               W1, gamma, rvar, pU, pF, tiles_u);

    int blocks = 148 * 8;
    edge_kernel<<<blocks, 256>>>(pU, pF, row, col, W2, b2, pC, out,
                                 E, n_users, n_foods);
}

// round 7
// speedup vs baseline: 2.8640x; 1.3098x over previous
#include <cuda_runtime.h>
#include <cuda_fp16.h>
#include <cstdint>
#include <cstddef>

#define EPSV 1e-5f
#define NUSERS_MAX 100000
#define NFOODS_MAX 50000

// Scratch (device globals, no allocations)
__device__ __align__(16) __half g_Uh[(size_t)NUSERS_MAX * 128];
__device__ __align__(16) __half g_Fh[(size_t)NFOODS_MAX * 128];
__device__ float  g_C[128];
__device__ int    g_is64;

__device__ __forceinline__ uint32_t smem_u32(const void* p) {
    uint32_t a;
    asm("{ .reg .u64 t; cvta.to.shared.u64 t, %1; cvt.u32.u64 %0, t; }"
        : "=r"(a) : "l"(p));
    return a;
}

__device__ __forceinline__ void ldm_x4(uint32_t& r0, uint32_t& r1,
                                       uint32_t& r2, uint32_t& r3, uint32_t a) {
    asm volatile("ldmatrix.sync.aligned.m8n8.x4.shared.b16 {%0,%1,%2,%3}, [%4];"
                 : "=r"(r0), "=r"(r1), "=r"(r2), "=r"(r3) : "r"(a));
}

__device__ __forceinline__ void mma_f16(float d[4], uint32_t a0, uint32_t a1,
                                        uint32_t a2, uint32_t a3,
                                        uint32_t b0, uint32_t b1) {
    asm volatile(
        "mma.sync.aligned.m16n8k16.row.col.f32.f16.f16.f32 "
        "{%0,%1,%2,%3}, {%4,%5,%6,%7}, {%8,%9}, {%0,%1,%2,%3};"
        : "+f"(d[0]), "+f"(d[1]), "+f"(d[2]), "+f"(d[3])
        : "r"(a0), "r"(a1), "r"(a2), "r"(a3), "r"(b0), "r"(b1));
}

// phys 16B-chunk index: XOR low 3 bits with row (conflict-free ldmatrix phases)
__device__ __forceinline__ int pchunk(int kc, int r) {
    return (kc & 8) | ((kc ^ r) & 7);
}

// ---------------------------------------------------------------------------
// fp16 HMMA GEMM: 128x128 tile per CTA, K=128 in one smem fill (64 KB).
// 8 warps tiled 4x2: warp = rows [(w&3)*32,+32) x cols [(w>>2)*64,+64).
// ---------------------------------------------------------------------------
__global__ void __launch_bounds__(256, 2)
gemm_mma(const float* __restrict__ zu, int Mu,
         const float* __restrict__ zf, int Mf,
         const float* __restrict__ W1,
         const float* __restrict__ gamma, const float* __restrict__ rvar,
         __half* __restrict__ Uh, __half* __restrict__ Fh, int tiles_u)
{
    extern __shared__ char smem[];     // A: [0,32768), B: [32768,65536)
    char* Ab = smem;
    char* Bb = smem + 32768;
    __shared__ float sS[128];

    int bid = blockIdx.x;
    const float* Z; int M; int koff; __half* out;
    if (bid < tiles_u) { Z = zu; M = Mu; koff = 0;   out = Uh; }
    else               { Z = zf; M = Mf; koff = 128; out = Fh; bid -= tiles_u; }
    const int m0 = bid * 128;

    const int tid  = threadIdx.x;
    const int wrp  = tid >> 5;
    const int lane = tid & 31;

    if (tid < 128) sS[tid] = gamma[tid] * rsqrtf(rvar[tid] + EPSV);

    // ---- fill: thread (kc = tid&15, row = tid>>4 + 16*pass) ----
    {
        const int kc = tid & 15;
        const int rb = tid >> 4;
#pragma unroll
        for (int pass = 0; pass < 8; pass++) {
            int r = rb + pass * 16;
            int pc16 = pchunk(kc, r) * 16;

            float4 lo = make_float4(0.f, 0.f, 0.f, 0.f);
            float4 hi = make_float4(0.f, 0.f, 0.f, 0.f);
            if (m0 + r < M) {
                lo = *(const float4*)(Z + (size_t)(m0 + r) * 128 + kc * 8);
                hi = *(const float4*)(Z + (size_t)(m0 + r) * 128 + kc * 8 + 4);
            }
            __half2 a0 = __floats2half2_rn(lo.x, lo.y);
            __half2 a1 = __floats2half2_rn(lo.z, lo.w);
            __half2 a2 = __floats2half2_rn(hi.x, hi.y);
            __half2 a3 = __floats2half2_rn(hi.z, hi.w);
            uint4 pa;
            pa.x = *(uint32_t*)&a0; pa.y = *(uint32_t*)&a1;
            pa.z = *(uint32_t*)&a2; pa.w = *(uint32_t*)&a3;
            *(uint4*)(Ab + r * 256 + pc16) = pa;

            float4 bl = *(const float4*)(W1 + (size_t)r * 256 + koff + kc * 8);
            float4 bh = *(const float4*)(W1 + (size_t)r * 256 + koff + kc * 8 + 4);
            __half2 b0 = __floats2half2_rn(bl.x, bl.y);
            __half2 b1 = __floats2half2_rn(bl.z, bl.w);
            __half2 b2 = __floats2half2_rn(bh.x, bh.y);
            __half2 b3 = __floats2half2_rn(bh.z, bh.w);
            uint4 pb;
            pb.x = *(uint32_t*)&b0; pb.y = *(uint32_t*)&b1;
            pb.z = *(uint32_t*)&b2; pb.w = *(uint32_t*)&b3;
            *(uint4*)(Bb + r * 256 + pc16) = pb;
        }
    }
    __syncthreads();

    // ---- compute: warp tile 32 rows x 64 cols ----
    const uint32_t Au = smem_u32(Ab);
    const uint32_t Bu = Au + 32768;
    const int g   = lane >> 3;
    const int idx = lane & 7;
    const int wr  = (wrp & 3) * 32;     // row base
    const int wc  = (wrp >> 2) * 64;    // col base

    float acc[2][8][4];
#pragma unroll
    for (int mt = 0; mt < 2; mt++)
#pragma unroll
        for (int j = 0; j < 8; j++)
#pragma unroll
            for (int q = 0; q < 4; q++) acc[mt][j][q] = 0.f;

#pragma unroll
    for (int kk = 0; kk < 8; kk++) {
        uint32_t a[2][4];
#pragma unroll
        for (int mt = 0; mt < 2; mt++) {
            int ar  = wr + mt * 16 + (g & 1) * 8 + idx;
            int akc = kk * 2 + (g >> 1);
            ldm_x4(a[mt][0], a[mt][1], a[mt][2], a[mt][3],
                   Au + ar * 256 + pchunk(akc, ar) * 16);
        }
#pragma unroll
        for (int jj = 0; jj < 4; jj++) {
            int bn  = wc + jj * 16 + (g >> 1) * 8 + idx;
            int bkc = kk * 2 + (g & 1);
            uint32_t b0, b1, b2, b3;
            ldm_x4(b0, b1, b2, b3, Bu + bn * 256 + pchunk(bkc, bn) * 16);
#pragma unroll
            for (int mt = 0; mt < 2; mt++) {
                mma_f16(acc[mt][2 * jj],     a[mt][0], a[mt][1], a[mt][2], a[mt][3], b0, b1);
                mma_f16(acc[mt][2 * jj + 1], a[mt][0], a[mt][1], a[mt][2], a[mt][3], b2, b3);
            }
        }
    }

    // ---- epilogue ----
    const int t  = lane & 3;
    const int qr = lane >> 2;
#pragma unroll
    for (int mt = 0; mt < 2; mt++) {
#pragma unroll
        for (int j = 0; j < 8; j++) {
            int n0 = wc + j * 8 + 2 * t;
            float s0 = sS[n0], s1 = sS[n0 + 1];
            int r0 = m0 + wr + mt * 16 + qr;
            int r1 = r0 + 8;
            if (r0 < M) {
                __half2 h = __floats2half2_rn(acc[mt][j][0] * s0, acc[mt][j][1] * s1);
                *(__half2*)(out + (size_t)r0 * 128 + n0) = h;
            }
            if (r1 < M) {
                __half2 h = __floats2half2_rn(acc[mt][j][2] * s0, acc[mt][j][3] * s1);
                *(__half2*)(out + (size_t)r1 * 128 + n0) = h;
            }
        }
    }
}

// ---------------------------------------------------------------------------
// Detect int64 vs int32 index buffers (odd 32-bit words all zero -> int64)
// ---------------------------------------------------------------------------
__global__ void detect_idx_dtype(const unsigned int* __restrict__ rowraw)
{
    int lane = threadIdx.x;
    unsigned int v = rowraw[2 * lane + 1];
    unsigned int any = __ballot_sync(0xffffffffu, v != 0u);
    if (lane == 0) g_is64 = (any == 0u) ? 1 : 0;
}

// c[n] = b1[n]*s + beta[n] - mean[n]*s
__global__ void prep_c(const float* __restrict__ b1, const float* __restrict__ gamma,
                       const float* __restrict__ beta, const float* __restrict__ mean,
                       const float* __restrict__ var, float* __restrict__ C)
{
    int n = threadIdx.x;
    float s = gamma[n] * rsqrtf(var[n] + EPSV);
    C[n] = b1[n] * s + beta[n] - mean[n] * s;
}

// ---------------------------------------------------------------------------
// Edge kernel: 4 edges/warp (8 lanes/edge), fp16 math, batched indices.
// Per batch of 32 edges: coalesced idx load + clamp once; per iteration
// broadcast via shfl. Dot accumulated in two half2 accs (depth 4 each).
// ---------------------------------------------------------------------------
__global__ void __launch_bounds__(256)
edge_kernel(const __half* __restrict__ U, const __half* __restrict__ F,
            const void* __restrict__ rowp, const void* __restrict__ colp,
            const float* __restrict__ W2, const float* __restrict__ b2,
            const float* __restrict__ C, float* __restrict__ out,
            int E, int n_users, int n_foods)
{
    __shared__ __half2 sWh[64];
    __shared__ __half2 sC[64];
    int tid = threadIdx.x;
    if (tid < 64) {
        float2 w2 = ((const float2*)W2)[tid];
        sWh[tid] = __floats2half2_rn(w2.x, w2.y);
        float2 c2 = ((const float2*)C)[tid];
        sC[tid] = __floats2half2_rn(c2.x, c2.y);
    }
    __syncthreads();

    const int lane = tid & 31;
    const int sub  = lane & 7;    // lane within edge (16 halves)
    const int g    = lane >> 3;   // edge within quad

    __half2 w[8], c[8];
#pragma unroll
    for (int i = 0; i < 8; i++) { w[i] = sWh[sub * 8 + i]; c[i] = sC[sub * 8 + i]; }
    const __half2 z2 = __half2half2(__ushort_as_half(0));

    const int warp = blockIdx.x * 8 + (tid >> 5);
    const int nw = gridDim.x * 8;
    const int is64 = g_is64;
    const float bias = b2[0] + 0.1f;

    const int*       row32 = (const int*)rowp;
    const int*       col32 = (const int*)colp;
    const long long* row64 = (const long long*)rowp;
    const long long* col64 = (const long long*)colp;
    const uint4* U4 = (const uint4*)U;
    const uint4* F4 = (const uint4*)F;

    for (int base = warp * 32; base < E; base += nw * 32) {
        // batched index load for 32 edges (lane -> edge base+lane)
        int myE = base + lane;
        int mi = myE < E ? myE : (E - 1);
        int ri, ci;
        if (is64) { ri = (int)row64[mi]; ci = (int)col64[mi]; }
        else      { ri = row32[mi];      ci = col32[mi]; }
        ri = min(max(ri, 0), n_users - 1);
        ci = min(max(ci, 0), n_foods - 1);

#pragma unroll
        for (int it = 0; it < 8; it++) {
            int j = it * 4 + g;
            int e = base + j;
            int rr = __shfl_sync(0xffffffffu, ri, j);
            int cc = __shfl_sync(0xffffffffu, ci, j);

            size_t ub = (size_t)rr * 16 + sub * 2;
            size_t fb = (size_t)cc * 16 + sub * 2;
            uint4 u0 = U4[ub], u1 = U4[ub + 1];
            uint4 f0 = F4[fb], f1 = F4[fb + 1];

            __half2 acc0 = z2, acc1 = z2;
#pragma unroll
            for (int q = 0; q < 4; q++) {
                uint32_t uq = (&u0.x)[q], fq = (&f0.x)[q];
                __half2 h = __hmax2(__hadd2(__hadd2(*(__half2*)&uq, *(__half2*)&fq), c[q]), z2);
                if (q & 1) acc1 = __hfma2(h, w[q], acc1);
                else       acc0 = __hfma2(h, w[q], acc0);
            }
#pragma unroll
            for (int q = 0; q < 4; q++) {
                uint32_t uq = (&u1.x)[q], fq = (&f1.x)[q];
                __half2 h = __hmax2(__hadd2(__hadd2(*(__half2*)&uq, *(__half2*)&fq), c[q + 4]), z2);
                if (q & 1) acc1 = __hfma2(h, w[q + 4], acc1);
                else       acc0 = __hfma2(h, w[q + 4], acc0);
            }
            float2 dv = __half22float2(__hadd2(acc0, acc1));
            float dot = dv.x + dv.y;

            dot += __shfl_xor_sync(0xffffffffu, dot, 4);
            dot += __shfl_xor_sync(0xffffffffu, dot, 2);
            dot += __shfl_xor_sync(0xffffffffu, dot, 1);

            if (sub == 0 && e < E)
                out[e] = 1.f / (1.f + __expf(-(dot + bias)));
        }
    }
}

// ---------------------------------------------------------------------------
// kernel_launch
// Inputs: z_user, z_food, row, col, W1, b1, gamma, beta, rmean, rvar, W2, b2
// ---------------------------------------------------------------------------
extern "C" void kernel_launch(void* const* d_in, const int* in_sizes, int n_in,
                              void* d_out, int out_size)
{
    const float* z_user = (const float*)d_in[0];
    const float* z_food = (const float*)d_in[1];
    const void*  row    = d_in[2];
    const void*  col    = d_in[3];
    const float* W1     = (const float*)d_in[4];
    const float* b1     = (const float*)d_in[5];
    const float* gamma  = (const float*)d_in[6];
    const float* beta   = (const float*)d_in[7];
    const float* rmean  = (const float*)d_in[8];
    const float* rvar   = (const float*)d_in[9];
    const float* W2     = (const float*)d_in[10];
    const float* b2     = (const float*)d_in[11];
    float*       out    = (float*)d_out;

    int n_users = in_sizes[0] / 128;
    int n_foods = in_sizes[1] / 128;
    int E       = in_sizes[2];
    if (n_users > NUSERS_MAX) n_users = NUSERS_MAX;
    if (n_foods > NFOODS_MAX) n_foods = NFOODS_MAX;

    __half *pU = nullptr, *pF = nullptr;
    float *pC = nullptr;
    cudaGetSymbolAddress((void**)&pU, g_Uh);
    cudaGetSymbolAddress((void**)&pF, g_Fh);
    cudaGetSymbolAddress((void**)&pC, g_C);

    detect_idx_dtype<<<1, 32>>>((const unsigned int*)row);
    prep_c<<<1, 128>>>(b1, gamma, beta, rmean, rvar, pC);

    int tiles_u = (n_users + 127) / 128;
    int tiles_f = (n_foods + 127) / 128;
    int smem = 65536;
    cudaFuncSetAttribute(gemm_mma, cudaFuncAttributeMaxDynamicSharedMemorySize, smem);
    gemm_mma<<<tiles_u + tiles_f, 256, smem>>>(z_user, n_users, z_food, n_foods,
                                               W1, gamma, rvar, pU, pF, tiles_u);

    int blocks = 148 * 8;
    edge_kernel<<<blocks, 256>>>(pU, pF, row, col, W2, b2, pC, out,
                                 E, n_users, n_foods);
}

// round 8
// speedup vs baseline: 3.0798x; 1.0754x over previous
#include <cuda_runtime.h>
#include <cuda_fp16.h>
#include <cstdint>
#include <cstddef>

#define EPSV 1e-5f
#define NUSERS_MAX 100000
#define NFOODS_MAX 50000

// Scratch (device globals, no allocations)
__device__ __align__(16) __half g_Uh[(size_t)NUSERS_MAX * 128];  // U*s + C
__device__ __align__(16) __half g_Fh[(size_t)NFOODS_MAX * 128];  // F*s

__device__ __forceinline__ uint32_t smem_u32(const void* p) {
    uint32_t a;
    asm("{ .reg .u64 t; cvta.to.shared.u64 t, %1; cvt.u32.u64 %0, t; }"
        : "=r"(a) : "l"(p));
    return a;
}

__device__ __forceinline__ void ldm_x4(uint32_t& r0, uint32_t& r1,
                                       uint32_t& r2, uint32_t& r3, uint32_t a) {
    asm volatile("ldmatrix.sync.aligned.m8n8.x4.shared.b16 {%0,%1,%2,%3}, [%4];"
                 : "=r"(r0), "=r"(r1), "=r"(r2), "=r"(r3) : "r"(a));
}

__device__ __forceinline__ void mma_f16(float d[4], uint32_t a0, uint32_t a1,
                                        uint32_t a2, uint32_t a3,
                                        uint32_t b0, uint32_t b1) {
    asm volatile(
        "mma.sync.aligned.m16n8k16.row.col.f32.f16.f16.f32 "
        "{%0,%1,%2,%3}, {%4,%5,%6,%7}, {%8,%9}, {%0,%1,%2,%3};"
        : "+f"(d[0]), "+f"(d[1]), "+f"(d[2]), "+f"(d[3])
        : "r"(a0), "r"(a1), "r"(a2), "r"(a3), "r"(b0), "r"(b1));
}

__device__ __forceinline__ int pchunk(int kc, int r) {
    return (kc & 8) | ((kc ^ r) & 7);
}

// ---------------------------------------------------------------------------
// fp16 HMMA GEMM: 128x128 tile per CTA, K=128 in one smem fill (64 KB).
// 8 warps tiled 4x2. Epilogue folds BN scale s[n]; for the U table it also
// adds C[n] = b1*s + beta - mean*s (exact fp32 add before fp16 round).
// ---------------------------------------------------------------------------
__global__ void __launch_bounds__(256, 2)
gemm_mma(const float* __restrict__ zu, int Mu,
         const float* __restrict__ zf, int Mf,
         const float* __restrict__ W1,
         const float* __restrict__ gamma, const float* __restrict__ rvar,
         const float* __restrict__ b1, const float* __restrict__ beta,
         const float* __restrict__ rmean,
         __half* __restrict__ Uh, __half* __restrict__ Fh, int tiles_u)
{
    extern __shared__ char smem[];     // A: [0,32768), B: [32768,65536)
    char* Ab = smem;
    char* Bb = smem + 32768;
    __shared__ float sS[128];
    __shared__ float sC[128];

    int bid = blockIdx.x;
    const float* Z; int M; int koff; __half* out; bool isU;
    if (bid < tiles_u) { Z = zu; M = Mu; koff = 0;   out = Uh; isU = true; }
    else               { Z = zf; M = Mf; koff = 128; out = Fh; isU = false; bid -= tiles_u; }
    const int m0 = bid * 128;

    const int tid  = threadIdx.x;
    const int wrp  = tid >> 5;
    const int lane = tid & 31;

    if (tid < 128) {
        float s = gamma[tid] * rsqrtf(rvar[tid] + EPSV);
        sS[tid] = s;
        sC[tid] = isU ? (b1[tid] * s + beta[tid] - rmean[tid] * s) : 0.f;
    }

    // ---- fill ----
    {
        const int kc = tid & 15;
        const int rb = tid >> 4;
#pragma unroll
        for (int pass = 0; pass < 8; pass++) {
            int r = rb + pass * 16;
            int pc16 = pchunk(kc, r) * 16;

            float4 lo = make_float4(0.f, 0.f, 0.f, 0.f);
            float4 hi = make_float4(0.f, 0.f, 0.f, 0.f);
            if (m0 + r < M) {
                lo = *(const float4*)(Z + (size_t)(m0 + r) * 128 + kc * 8);
                hi = *(const float4*)(Z + (size_t)(m0 + r) * 128 + kc * 8 + 4);
            }
            __half2 a0 = __floats2half2_rn(lo.x, lo.y);
            __half2 a1 = __floats2half2_rn(lo.z, lo.w);
            __half2 a2 = __floats2half2_rn(hi.x, hi.y);
            __half2 a3 = __floats2half2_rn(hi.z, hi.w);
            uint4 pa;
            pa.x = *(uint32_t*)&a0; pa.y = *(uint32_t*)&a1;
            pa.z = *(uint32_t*)&a2; pa.w = *(uint32_t*)&a3;
            *(uint4*)(Ab + r * 256 + pc16) = pa;

            float4 bl = *(const float4*)(W1 + (size_t)r * 256 + koff + kc * 8);
            float4 bh = *(const float4*)(W1 + (size_t)r * 256 + koff + kc * 8 + 4);
            __half2 b0 = __floats2half2_rn(bl.x, bl.y);
            __half2 b1h = __floats2half2_rn(bl.z, bl.w);
            __half2 b2 = __floats2half2_rn(bh.x, bh.y);
            __half2 b3 = __floats2half2_rn(bh.z, bh.w);
            uint4 pb;
            pb.x = *(uint32_t*)&b0; pb.y = *(uint32_t*)&b1h;
            pb.z = *(uint32_t*)&b2; pb.w = *(uint32_t*)&b3;
            *(uint4*)(Bb + r * 256 + pc16) = pb;
        }
    }
    __syncthreads();

    // ---- compute: warp tile 32 rows x 64 cols ----
    const uint32_t Au = smem_u32(Ab);
    const uint32_t Bu = Au + 32768;
    const int g   = lane >> 3;
    const int idx = lane & 7;
    const int wr  = (wrp & 3) * 32;
    const int wc  = (wrp >> 2) * 64;

    float acc[2][8][4];
#pragma unroll
    for (int mt = 0; mt < 2; mt++)
#pragma unroll
        for (int j = 0; j < 8; j++)
#pragma unroll
            for (int q = 0; q < 4; q++) acc[mt][j][q] = 0.f;

#pragma unroll
    for (int kk = 0; kk < 8; kk++) {
        uint32_t a[2][4];
#pragma unroll
        for (int mt = 0; mt < 2; mt++) {
            int ar  = wr + mt * 16 + (g & 1) * 8 + idx;
            int akc = kk * 2 + (g >> 1);
            ldm_x4(a[mt][0], a[mt][1], a[mt][2], a[mt][3],
                   Au + ar * 256 + pchunk(akc, ar) * 16);
        }
#pragma unroll
        for (int jj = 0; jj < 4; jj++) {
            int bn  = wc + jj * 16 + (g >> 1) * 8 + idx;
            int bkc = kk * 2 + (g & 1);
            uint32_t b0, b1x, b2, b3;
            ldm_x4(b0, b1x, b2, b3, Bu + bn * 256 + pchunk(bkc, bn) * 16);
#pragma unroll
            for (int mt = 0; mt < 2; mt++) {
                mma_f16(acc[mt][2 * jj],     a[mt][0], a[mt][1], a[mt][2], a[mt][3], b0, b1x);
                mma_f16(acc[mt][2 * jj + 1], a[mt][0], a[mt][1], a[mt][2], a[mt][3], b2, b3);
            }
        }
    }

    // ---- epilogue: h = acc*s (+ C for U table) ----
    const int t  = lane & 3;
    const int qr = lane >> 2;
#pragma unroll
    for (int mt = 0; mt < 2; mt++) {
#pragma unroll
        for (int j = 0; j < 8; j++) {
            int n0 = wc + j * 8 + 2 * t;
            float s0 = sS[n0], s1 = sS[n0 + 1];
            float c0 = sC[n0], c1 = sC[n0 + 1];
            int r0 = m0 + wr + mt * 16 + qr;
            int r1 = r0 + 8;
            if (r0 < M) {
                __half2 h = __floats2half2_rn(fmaf(acc[mt][j][0], s0, c0),
                                              fmaf(acc[mt][j][1], s1, c1));
                *(__half2*)(out + (size_t)r0 * 128 + n0) = h;
            }
            if (r1 < M) {
                __half2 h = __floats2half2_rn(fmaf(acc[mt][j][2], s0, c0),
                                              fmaf(acc[mt][j][3], s1, c1));
                *(__half2*)(out + (size_t)r1 * 128 + n0) = h;
            }
        }
    }
}

// ---------------------------------------------------------------------------
// Edge kernel: 4 edges/warp (8 lanes/edge), fp16 math, batched indices,
// double-buffered gathers. is64 detection done per-block (no extra launch).
// out[e] = sigmoid( w . relu(U'[row] + F[col]) + bias )
// ---------------------------------------------------------------------------
__global__ void __launch_bounds__(256)
edge_kernel(const __half* __restrict__ U, const __half* __restrict__ F,
            const void* __restrict__ rowp, const void* __restrict__ colp,
            const float* __restrict__ W2, const float* __restrict__ b2,
            float* __restrict__ out, int E, int n_users, int n_foods)
{
    __shared__ __half2 sWh[64];
    __shared__ int s_is64;
    int tid = threadIdx.x;
    if (tid < 64) {
        float2 w2 = ((const float2*)W2)[tid];
        sWh[tid] = __floats2half2_rn(w2.x, w2.y);
    }
    if (tid < 32) {
        unsigned int v = ((const unsigned int*)rowp)[2 * tid + 1];
        unsigned int any = __ballot_sync(0xffffffffu, v != 0u);
        if (tid == 0) s_is64 = (any == 0u) ? 1 : 0;
    }
    __syncthreads();

    const int lane = tid & 31;
    const int sub  = lane & 7;    // lane within edge
    const int g    = lane >> 3;   // edge within quad

    __half2 w[8];
#pragma unroll
    for (int i = 0; i < 8; i++) w[i] = sWh[sub * 8 + i];
    const __half2 z2 = __half2half2(__ushort_as_half(0));

    const int warp = blockIdx.x * 8 + (tid >> 5);
    const int nw = gridDim.x * 8;
    const int is64 = s_is64;
    const float bias = b2[0] + 0.1f;

    const int*       row32 = (const int*)rowp;
    const int*       col32 = (const int*)colp;
    const long long* row64 = (const long long*)rowp;
    const long long* col64 = (const long long*)colp;
    const uint4* U4 = (const uint4*)U;
    const uint4* F4 = (const uint4*)F;

    for (int base = warp * 32; base < E; base += nw * 32) {
        int myE = base + lane;
        int mi = myE < E ? myE : (E - 1);
        int ri, ci;
        if (is64) { ri = (int)row64[mi]; ci = (int)col64[mi]; }
        else      { ri = row32[mi];      ci = col32[mi]; }
        ri = min(max(ri, 0), n_users - 1);
        ci = min(max(ci, 0), n_foods - 1);

        // prefetch iteration 0
        uint4 bu0[2], bu1[2], bf0[2], bf1[2];
        {
            int rr = __shfl_sync(0xffffffffu, ri, g);
            int cc = __shfl_sync(0xffffffffu, ci, g);
            size_t ub = (size_t)rr * 16 + sub * 2;
            size_t fb = (size_t)cc * 16 + sub * 2;
            bu0[0] = U4[ub]; bu1[0] = U4[ub + 1];
            bf0[0] = F4[fb]; bf1[0] = F4[fb + 1];
        }

#pragma unroll
        for (int it = 0; it < 8; it++) {
            int cur = it & 1, nxt = cur ^ 1;
            if (it < 7) {
                int j2 = (it + 1) * 4 + g;
                int rr = __shfl_sync(0xffffffffu, ri, j2);
                int cc = __shfl_sync(0xffffffffu, ci, j2);
                size_t ub = (size_t)rr * 16 + sub * 2;
                size_t fb = (size_t)cc * 16 + sub * 2;
                bu0[nxt] = U4[ub]; bu1[nxt] = U4[ub + 1];
                bf0[nxt] = F4[fb]; bf1[nxt] = F4[fb + 1];
            }

            __half2 acc0 = z2, acc1 = z2;
#pragma unroll
            for (int q = 0; q < 4; q++) {
                uint32_t uq = (&bu0[cur].x)[q], fq = (&bf0[cur].x)[q];
                __half2 h = __hmax2(__hadd2(*(__half2*)&uq, *(__half2*)&fq), z2);
                if (q & 1) acc1 = __hfma2(h, w[q], acc1);
                else       acc0 = __hfma2(h, w[q], acc0);
            }
#pragma unroll
            for (int q = 0; q < 4; q++) {
                uint32_t uq = (&bu1[cur].x)[q], fq = (&bf1[cur].x)[q];
                __half2 h = __hmax2(__hadd2(*(__half2*)&uq, *(__half2*)&fq), z2);
                if (q & 1) acc1 = __hfma2(h, w[q + 4], acc1);
                else       acc0 = __hfma2(h, w[q + 4], acc0);
            }
            float2 dv = __half22float2(__hadd2(acc0, acc1));
            float dot = dv.x + dv.y;

            dot += __shfl_xor_sync(0xffffffffu, dot, 4);
            dot += __shfl_xor_sync(0xffffffffu, dot, 2);
            dot += __shfl_xor_sync(0xffffffffu, dot, 1);

            int e = base + it * 4 + g;
            if (sub == 0 && e < E)
                out[e] = 1.f / (1.f + __expf(-(dot + bias)));
        }
    }
}

// ---------------------------------------------------------------------------
// kernel_launch
// Inputs: z_user, z_food, row, col, W1, b1, gamma, beta, rmean, rvar, W2, b2
// ---------------------------------------------------------------------------
extern "C" void kernel_launch(void* const* d_in, const int* in_sizes, int n_in,
                              void* d_out, int out_size)
{
    const float* z_user = (const float*)d_in[0];
    const float* z_food = (const float*)d_in[1];
    const void*  row    = d_in[2];
    const void*  col    = d_in[3];
    const float* W1     = (const float*)d_in[4];
    const float* b1     = (const float*)d_in[5];
    const float* gamma  = (const float*)d_in[6];
    const float* beta   = (const float*)d_in[7];
    const float* rmean  = (const float*)d_in[8];
    const float* rvar   = (const float*)d_in[9];
    const float* W2     = (const float*)d_in[10];
    const float* b2     = (const float*)d_in[11];
    float*       out    = (float*)d_out;

    int n_users = in_sizes[0] / 128;
    int n_foods = in_sizes[1] / 128;
    int E       = in_sizes[2];
    if (n_users > NUSERS_MAX) n_users = NUSERS_MAX;
    if (n_foods > NFOODS_MAX) n_foods = NFOODS_MAX;

    __half *pU = nullptr, *pF = nullptr;
    cudaGetSymbolAddress((void**)&pU, g_Uh);
    cudaGetSymbolAddress((void**)&pF, g_Fh);

    int tiles_u = (n_users + 127) / 128;
    int tiles_f = (n_foods + 127) / 128;
    int smem = 65536;
    cudaFuncSetAttribute(gemm_mma, cudaFuncAttributeMaxDynamicSharedMemorySize, smem);
    gemm_mma<<<tiles_u + tiles_f, 256, smem>>>(z_user, n_users, z_food, n_foods,
                                               W1, gamma, rvar, b1, beta, rmean,
                                               pU, pF, tiles_u);

    int blocks = 148 * 8;
    edge_kernel<<<blocks, 256>>>(pU, pF, row, col, W2, b2, out,
                                 E, n_users, n_foods);
}

// round 9
// speedup vs baseline: 3.2931x; 1.0693x over previous
#include <cuda_runtime.h>
#include <cuda_fp16.h>
#include <cstdint>
#include <cstddef>

#define EPSV 1e-5f
#define NUSERS_MAX 100000
#define NFOODS_MAX 50000

// Scratch (device globals, no allocations)
__device__ __align__(16) __half g_Uh[(size_t)NUSERS_MAX * 128];  // U*s + C
__device__ __align__(16) __half g_Fh[(size_t)NFOODS_MAX * 128];  // F*s

__device__ __forceinline__ uint32_t smem_u32(const void* p) {
    uint32_t a;
    asm("{ .reg .u64 t; cvta.to.shared.u64 t, %1; cvt.u32.u64 %0, t; }"
        : "=r"(a) : "l"(p));
    return a;
}

__device__ __forceinline__ void ldm_x4(uint32_t& r0, uint32_t& r1,
                                       uint32_t& r2, uint32_t& r3, uint32_t a) {
    asm volatile("ldmatrix.sync.aligned.m8n8.x4.shared.b16 {%0,%1,%2,%3}, [%4];"
                 : "=r"(r0), "=r"(r1), "=r"(r2), "=r"(r3) : "r"(a));
}

__device__ __forceinline__ void mma_f16(float d[4], uint32_t a0, uint32_t a1,
                                        uint32_t a2, uint32_t a3,
                                        uint32_t b0, uint32_t b1) {
    asm volatile(
        "mma.sync.aligned.m16n8k16.row.col.f32.f16.f16.f32 "
        "{%0,%1,%2,%3}, {%4,%5,%6,%7}, {%8,%9}, {%0,%1,%2,%3};"
        : "+f"(d[0]), "+f"(d[1]), "+f"(d[2]), "+f"(d[3])
        : "r"(a0), "r"(a1), "r"(a2), "r"(a3), "r"(b0), "r"(b1));
}

__device__ __forceinline__ int pchunk(int kc, int r) {
    return (kc & 8) | ((kc ^ r) & 7);
}

// ---------------------------------------------------------------------------
// fp16 HMMA GEMM: 128x128 tile per CTA, K=128 in one smem fill (64 KB).
// 8 warps tiled 4x2. Epilogue folds BN scale s[n] (+ C[n] for the U table),
// then transposes through smem so GMEM writes are full 256B rows (STG.128).
// ---------------------------------------------------------------------------
__global__ void __launch_bounds__(256, 2)
gemm_mma(const float* __restrict__ zu, int Mu,
         const float* __restrict__ zf, int Mf,
         const float* __restrict__ W1,
         const float* __restrict__ gamma, const float* __restrict__ rvar,
         const float* __restrict__ b1, const float* __restrict__ beta,
         const float* __restrict__ rmean,
         __half* __restrict__ Uh, __half* __restrict__ Fh, int tiles_u)
{
    extern __shared__ char smem[];     // A: [0,32768), B: [32768,65536)
    char* Ab = smem;
    char* Bb = smem + 32768;
    __shared__ float sS[128];
    __shared__ float sC[128];

    int bid = blockIdx.x;
    const float* Z; int M; int koff; __half* out; bool isU;
    if (bid < tiles_u) { Z = zu; M = Mu; koff = 0;   out = Uh; isU = true; }
    else               { Z = zf; M = Mf; koff = 128; out = Fh; isU = false; bid -= tiles_u; }
    const int m0 = bid * 128;

    const int tid  = threadIdx.x;
    const int wrp  = tid >> 5;
    const int lane = tid & 31;

    if (tid < 128) {
        float s = gamma[tid] * rsqrtf(rvar[tid] + EPSV);
        sS[tid] = s;
        sC[tid] = isU ? (b1[tid] * s + beta[tid] - rmean[tid] * s) : 0.f;
    }

    // ---- fill ----
    {
        const int kc = tid & 15;
        const int rb = tid >> 4;
#pragma unroll
        for (int pass = 0; pass < 8; pass++) {
            int r = rb + pass * 16;
            int pc16 = pchunk(kc, r) * 16;

            float4 lo = make_float4(0.f, 0.f, 0.f, 0.f);
            float4 hi = make_float4(0.f, 0.f, 0.f, 0.f);
            if (m0 + r < M) {
                lo = *(const float4*)(Z + (size_t)(m0 + r) * 128 + kc * 8);
                hi = *(const float4*)(Z + (size_t)(m0 + r) * 128 + kc * 8 + 4);
            }
            __half2 a0 = __floats2half2_rn(lo.x, lo.y);
            __half2 a1 = __floats2half2_rn(lo.z, lo.w);
            __half2 a2 = __floats2half2_rn(hi.x, hi.y);
            __half2 a3 = __floats2half2_rn(hi.z, hi.w);
            uint4 pa;
            pa.x = *(uint32_t*)&a0; pa.y = *(uint32_t*)&a1;
            pa.z = *(uint32_t*)&a2; pa.w = *(uint32_t*)&a3;
            *(uint4*)(Ab + r * 256 + pc16) = pa;

            float4 bl = *(const float4*)(W1 + (size_t)r * 256 + koff + kc * 8);
            float4 bh = *(const float4*)(W1 + (size_t)r * 256 + koff + kc * 8 + 4);
            __half2 b0 = __floats2half2_rn(bl.x, bl.y);
            __half2 b1h = __floats2half2_rn(bl.z, bl.w);
            __half2 b2 = __floats2half2_rn(bh.x, bh.y);
            __half2 b3 = __floats2half2_rn(bh.z, bh.w);
            uint4 pb;
            pb.x = *(uint32_t*)&b0; pb.y = *(uint32_t*)&b1h;
            pb.z = *(uint32_t*)&b2; pb.w = *(uint32_t*)&b3;
            *(uint4*)(Bb + r * 256 + pc16) = pb;
        }
    }
    __syncthreads();

    // ---- compute: warp tile 32 rows x 64 cols ----
    const uint32_t Au = smem_u32(Ab);
    const uint32_t Bu = Au + 32768;
    const int g   = lane >> 3;
    const int idx = lane & 7;
    const int wr  = (wrp & 3) * 32;
    const int wc  = (wrp >> 2) * 64;

    float acc[2][8][4];
#pragma unroll
    for (int mt = 0; mt < 2; mt++)
#pragma unroll
        for (int j = 0; j < 8; j++)
#pragma unroll
            for (int q = 0; q < 4; q++) acc[mt][j][q] = 0.f;

#pragma unroll
    for (int kk = 0; kk < 8; kk++) {
        uint32_t a[2][4];
#pragma unroll
        for (int mt = 0; mt < 2; mt++) {
            int ar  = wr + mt * 16 + (g & 1) * 8 + idx;
            int akc = kk * 2 + (g >> 1);
            ldm_x4(a[mt][0], a[mt][1], a[mt][2], a[mt][3],
                   Au + ar * 256 + pchunk(akc, ar) * 16);
        }
#pragma unroll
        for (int jj = 0; jj < 4; jj++) {
            int bn  = wc + jj * 16 + (g >> 1) * 8 + idx;
            int bkc = kk * 2 + (g & 1);
            uint32_t b0, b1x, b2, b3;
            ldm_x4(b0, b1x, b2, b3, Bu + bn * 256 + pchunk(bkc, bn) * 16);
#pragma unroll
            for (int mt = 0; mt < 2; mt++) {
                mma_f16(acc[mt][2 * jj],     a[mt][0], a[mt][1], a[mt][2], a[mt][3], b0, b1x);
                mma_f16(acc[mt][2 * jj + 1], a[mt][0], a[mt][1], a[mt][2], a[mt][3], b2, b3);
            }
        }
    }
    __syncthreads();   // done reading A/B smem

    // ---- epilogue stage 1: scaled fp16 tile -> smem (swizzled, conflict-free)
    // smem addr for (row, col n): row*256 + ((chunk ^ (row&7))*16) + (n*2)&15,
    // chunk = n>>3. Here n0 = wc + j*8 + 2t -> chunk = wc/8 + j, within = 4t.
    const int t  = lane & 3;
    const int qr = lane >> 2;
#pragma unroll
    for (int mt = 0; mt < 2; mt++) {
#pragma unroll
        for (int j = 0; j < 8; j++) {
            int n0 = wc + j * 8 + 2 * t;
            int ch = (wc >> 3) + j;
            float s0 = sS[n0], s1 = sS[n0 + 1];
            float c0 = sC[n0], c1 = sC[n0 + 1];
            int r0 = wr + mt * 16 + qr;
            int r1 = r0 + 8;
            __half2 h0 = __floats2half2_rn(fmaf(acc[mt][j][0], s0, c0),
                                           fmaf(acc[mt][j][1], s1, c1));
            __half2 h1 = __floats2half2_rn(fmaf(acc[mt][j][2], s0, c0),
                                           fmaf(acc[mt][j][3], s1, c1));
            *(__half2*)(Ab + r0 * 256 + ((ch ^ (r0 & 7)) * 16) + 4 * t) = h0;
            *(__half2*)(Ab + r1 * 256 + ((ch ^ (r1 & 7)) * 16) + 4 * t) = h1;
        }
    }
    __syncthreads();

    // ---- epilogue stage 2: coalesced 256B-row stores ----
#pragma unroll
    for (int pass = 0; pass < 8; pass++) {
        int i   = tid + pass * 256;     // 0..2047 16B chunks
        int row = i >> 4;
        int ch  = i & 15;
        uint4 v = *(uint4*)(Ab + row * 256 + ((ch ^ (row & 7)) * 16));
        int gr = m0 + row;
        if (gr < M)
            *(uint4*)(out + (size_t)gr * 128 + ch * 8) = v;
    }
}

// ---------------------------------------------------------------------------
// Edge kernel: 4 edges/warp (8 lanes/edge), fp16 math, batched indices,
// double-buffered gathers. is64 detection done per-block (no extra launch).
// out[e] = sigmoid( w . relu(U'[row] + F[col]) + bias )
// ---------------------------------------------------------------------------
__global__ void __launch_bounds__(256)
edge_kernel(const __half* __restrict__ U, const __half* __restrict__ F,
            const void* __restrict__ rowp, const void* __restrict__ colp,
            const float* __restrict__ W2, const float* __restrict__ b2,
            float* __restrict__ out, int E, int n_users, int n_foods)
{
    __shared__ __half2 sWh[64];
    __shared__ int s_is64;
    int tid = threadIdx.x;
    if (tid < 64) {
        float2 w2 = ((const float2*)W2)[tid];
        sWh[tid] = __floats2half2_rn(w2.x, w2.y);
    }
    if (tid < 32) {
        unsigned int v = ((const unsigned int*)rowp)[2 * tid + 1];
        unsigned int any = __ballot_sync(0xffffffffu, v != 0u);
        if (tid == 0) s_is64 = (any == 0u) ? 1 : 0;
    }
    __syncthreads();

    const int lane = tid & 31;
    const int sub  = lane & 7;
    const int g    = lane >> 3;

    __half2 w[8];
#pragma unroll
    for (int i = 0; i < 8; i++) w[i] = sWh[sub * 8 + i];
    const __half2 z2 = __half2half2(__ushort_as_half(0));

    const int warp = blockIdx.x * 8 + (tid >> 5);
    const int nw = gridDim.x * 8;
    const int is64 = s_is64;
    const float bias = b2[0] + 0.1f;

    const int*       row32 = (const int*)rowp;
    const int*       col32 = (const int*)colp;
    const long long* row64 = (const long long*)rowp;
    const long long* col64 = (const long long*)colp;
    const uint4* U4 = (const uint4*)U;
    const uint4* F4 = (const uint4*)F;

    for (int base = warp * 32; base < E; base += nw * 32) {
        int myE = base + lane;
        int mi = myE < E ? myE : (E - 1);
        int ri, ci;
        if (is64) { ri = (int)row64[mi]; ci = (int)col64[mi]; }
        else      { ri = row32[mi];      ci = col32[mi]; }
        ri = min(max(ri, 0), n_users - 1);
        ci = min(max(ci, 0), n_foods - 1);

        uint4 bu0[2], bu1[2], bf0[2], bf1[2];
        {
            int rr = __shfl_sync(0xffffffffu, ri, g);
            int cc = __shfl_sync(0xffffffffu, ci, g);
            size_t ub = (size_t)rr * 16 + sub * 2;
            size_t fb = (size_t)cc * 16 + sub * 2;
            bu0[0] = U4[ub]; bu1[0] = U4[ub + 1];
            bf0[0] = F4[fb]; bf1[0] = F4[fb + 1];
        }

#pragma unroll
        for (int it = 0; it < 8; it++) {
            int cur = it & 1, nxt = cur ^ 1;
            if (it < 7) {
                int j2 = (it + 1) * 4 + g;
                int rr = __shfl_sync(0xffffffffu, ri, j2);
                int cc = __shfl_sync(0xffffffffu, ci, j2);
                size_t ub = (size_t)rr * 16 + sub * 2;
                size_t fb = (size_t)cc * 16 + sub * 2;
                bu0[nxt] = U4[ub]; bu1[nxt] = U4[ub + 1];
                bf0[nxt] = F4[fb]; bf1[nxt] = F4[fb + 1];
            }

            __half2 acc0 = z2, acc1 = z2;
#pragma unroll
            for (int q = 0; q < 4; q++) {
                uint32_t uq = (&bu0[cur].x)[q], fq = (&bf0[cur].x)[q];
                __half2 h = __hmax2(__hadd2(*(__half2*)&uq, *(__half2*)&fq), z2);
                if (q & 1) acc1 = __hfma2(h, w[q], acc1);
                else       acc0 = __hfma2(h, w[q], acc0);
            }
#pragma unroll
            for (int q = 0; q < 4; q++) {
                uint32_t uq = (&bu1[cur].x)[q], fq = (&bf1[cur].x)[q];
                __half2 h = __hmax2(__hadd2(*(__half2*)&uq, *(__half2*)&fq), z2);
                if (q & 1) acc1 = __hfma2(h, w[q + 4], acc1);
                else       acc0 = __hfma2(h, w[q + 4], acc0);
            }
            float2 dv = __half22float2(__hadd2(acc0, acc1));
            float dot = dv.x + dv.y;

            dot += __shfl_xor_sync(0xffffffffu, dot, 4);
            dot += __shfl_xor_sync(0xffffffffu, dot, 2);
            dot += __shfl_xor_sync(0xffffffffu, dot, 1);

            int e = base + it * 4 + g;
            if (sub == 0 && e < E)
                out[e] = 1.f / (1.f + __expf(-(dot + bias)));
        }
    }
}

// ---------------------------------------------------------------------------
// kernel_launch
// Inputs: z_user, z_food, row, col, W1, b1, gamma, beta, rmean, rvar, W2, b2
// ---------------------------------------------------------------------------
extern "C" void kernel_launch(void* const* d_in, const int* in_sizes, int n_in,
                              void* d_out, int out_size)
{
    const float* z_user = (const float*)d_in[0];
    const float* z_food = (const float*)d_in[1];
    const void*  row    = d_in[2];
    const void*  col    = d_in[3];
    const float* W1     = (const float*)d_in[4];
    const float* b1     = (const float*)d_in[5];
    const float* gamma  = (const float*)d_in[6];
    const float* beta   = (const float*)d_in[7];
    const float* rmean  = (const float*)d_in[8];
    const float* rvar   = (const float*)d_in[9];
    const float* W2     = (const float*)d_in[10];
    const float* b2     = (const float*)d_in[11];
    float*       out    = (float*)d_out;

    int n_users = in_sizes[0] / 128;
    int n_foods = in_sizes[1] / 128;
    int E       = in_sizes[2];
    if (n_users > NUSERS_MAX) n_users = NUSERS_MAX;
    if (n_foods > NFOODS_MAX) n_foods = NFOODS_MAX;

    __half *pU = nullptr, *pF = nullptr;
    cudaGetSymbolAddress((void**)&pU, g_Uh);
    cudaGetSymbolAddress((void**)&pF, g_Fh);

    int tiles_u = (n_users + 127) / 128;
    int tiles_f = (n_foods + 127) / 128;
    int smem = 65536;
    cudaFuncSetAttribute(gemm_mma, cudaFuncAttributeMaxDynamicSharedMemorySize, smem);
    gemm_mma<<<tiles_u + tiles_f, 256, smem>>>(z_user, n_users, z_food, n_foods,
                                               W1, gamma, rvar, b1, beta, rmean,
                                               pU, pF, tiles_u);

    int blocks = 148 * 8;
    edge_kernel<<<blocks, 256>>>(pU, pF, row, col, W2, b2, out,
                                 E, n_users, n_foods);
}